// round 1
// baseline (speedup 1.0000x reference)
#include <cuda_runtime.h>
#include <math.h>

#define N2 4096
#define NB 2048
#define D 128
#define TAU_INV 10.0f

#define BI 128          // i-rows per block
#define BJ 64           // j-cols per chunk
#define JSPLITS 16      // j-range splits across blockIdx.y
#define CHUNKS 4        // (N2/JSPLITS)/BJ = 256/64

// ---------------- device scratch (no allocation allowed) ----------------
__device__ float g_Q[N2 * D];            // normalized rows
__device__ int   g_lbl[N2];              // labels widened to int
__device__ float g_cnt[N2];              // positive counts per row
__device__ float g_Zp[JSPLITS * N2];     // partial sum exp per j-split
__device__ float g_Sp[JSPLITS * N2];     // partial masked logit sum per j-split

// ---------------- kernel 1: L2-normalize rows, widen labels ----------------
__global__ void normalize_kernel(const float* __restrict__ zi,
                                 const float* __restrict__ zj,
                                 const long long* __restrict__ y) {
    int row  = blockIdx.x * 8 + (threadIdx.x >> 5);
    int lane = threadIdx.x & 31;
    const float* src = (row < NB) ? (zi + (size_t)row * D)
                                  : (zj + (size_t)(row - NB) * D);
    float4 v = ((const float4*)src)[lane];
    float ss = v.x * v.x + v.y * v.y + v.z * v.z + v.w * v.w;
#pragma unroll
    for (int m = 16; m; m >>= 1) ss += __shfl_xor_sync(0xffffffffu, ss, m);
    float inv = rsqrtf(fmaxf(ss, 1e-30f));
    float4 o = make_float4(v.x * inv, v.y * inv, v.z * inv, v.w * inv);
    ((float4*)(g_Q + (size_t)row * D))[lane] = o;
    if (lane == 0) g_lbl[row] = (int)y[row & (NB - 1)];
}

// ---------------- kernel 2: positive counts: cnt_i = #{j != i : lbl_j == lbl_i} ----------------
__global__ void cnt_kernel() {
    __shared__ int sl[N2];
    for (int t = threadIdx.x; t < N2; t += blockDim.x) sl[t] = g_lbl[t];
    __syncthreads();
    int i = blockIdx.x * blockDim.x + threadIdx.x;
    int my = sl[i];
    int c = 0;
#pragma unroll 8
    for (int j = 0; j < N2; j++) c += (sl[j] == my);
    g_cnt[i] = (float)(c - 1);
}

// ---------------- kernel 3: fused sim + softmax statistics ----------------
struct MainSmem {
    float sQ[BI * D];     // i-tile, row-major   (A loads are half-warp broadcasts)
    float sKt[D * BJ];    // j-chunk, d-major    (B loads: float4 over j, conflict-free)
    int   li[BI];
    int   lj[BJ];
};

__global__ void __launch_bounds__(256, 2) sim_kernel() {
    extern __shared__ char raw[];
    MainSmem* sm = (MainSmem*)raw;
    const int tid = threadIdx.x;
    const int tx = tid & 15;          // j-group (4 cols each)
    const int ty = tid >> 4;          // i-group (8 rows each)
    const int ibase  = blockIdx.x * BI;
    const int jbase0 = blockIdx.y * (BJ * CHUNKS);

    // load i-tile (coalesced LDG, conflict-free STS.128)
    {
        int d4 = tid & 31, r0 = tid >> 5;
        for (int r = r0; r < BI; r += 8) {
            float4 v = ((const float4*)(g_Q + (size_t)(ibase + r) * D))[d4];
            ((float4*)sm->sQ)[r * 32 + d4] = v;
        }
    }
    for (int t = tid; t < BI; t += 256) sm->li[t] = g_lbl[ibase + t];

    float zacc[8], sacc[8];
#pragma unroll
    for (int ii = 0; ii < 8; ii++) { zacc[ii] = 0.f; sacc[ii] = 0.f; }

    for (int c = 0; c < CHUNKS; c++) {
        const int jbase = jbase0 + c * BJ;
        __syncthreads();  // previous chunk fully consumed (also covers first-iter sQ/li)
        // load j-chunk transposed: lanes walk rows (conflict-free STS), strided LDG (L2-hit)
        for (int idx = tid; idx < BJ * 32; idx += 256) {
            int row = idx & 63, d4 = idx >> 6;
            float4 v = ((const float4*)(g_Q + (size_t)(jbase + row) * D))[d4];
            sm->sKt[(4 * d4 + 0) * BJ + row] = v.x;
            sm->sKt[(4 * d4 + 1) * BJ + row] = v.y;
            sm->sKt[(4 * d4 + 2) * BJ + row] = v.z;
            sm->sKt[(4 * d4 + 3) * BJ + row] = v.w;
        }
        for (int t = tid; t < BJ; t += 256) sm->lj[t] = g_lbl[jbase + t];
        __syncthreads();

        float acc[8][4];
#pragma unroll
        for (int ii = 0; ii < 8; ii++)
#pragma unroll
            for (int jj = 0; jj < 4; jj++) acc[ii][jj] = 0.f;

        for (int d4 = 0; d4 < 32; d4++) {   // rolled: keep I$ footprint small
            float a[8][4];
#pragma unroll
            for (int ii = 0; ii < 8; ii++) {
                float4 t4 = *(const float4*)&sm->sQ[(ty * 8 + ii) * D + d4 * 4];
                a[ii][0] = t4.x; a[ii][1] = t4.y; a[ii][2] = t4.z; a[ii][3] = t4.w;
            }
#pragma unroll
            for (int dd = 0; dd < 4; dd++) {
                float4 b = *(const float4*)&sm->sKt[(d4 * 4 + dd) * BJ + tx * 4];
#pragma unroll
                for (int ii = 0; ii < 8; ii++) {
                    acc[ii][0] = fmaf(a[ii][dd], b.x, acc[ii][0]);
                    acc[ii][1] = fmaf(a[ii][dd], b.y, acc[ii][1]);
                    acc[ii][2] = fmaf(a[ii][dd], b.z, acc[ii][2]);
                    acc[ii][3] = fmaf(a[ii][dd], b.w, acc[ii][3]);
                }
            }
        }

        // epilogue: fold this chunk into per-row Z / S accumulators
#pragma unroll
        for (int ii = 0; ii < 8; ii++) {
            int gi  = ibase + ty * 8 + ii;
            int myl = sm->li[ty * 8 + ii];
#pragma unroll
            for (int jj = 0; jj < 4; jj++) {
                int gj = jbase + tx * 4 + jj;
                float logit = acc[ii][jj] * TAU_INV;
                if (gi != gj) {
                    zacc[ii] += __expf(logit);
                    if (sm->lj[tx * 4 + jj] == myl) sacc[ii] += logit;
                }
            }
        }
    }

    // reduce over the 16 tx-threads sharing each row (lanes 0-15 / 16-31 halves)
#pragma unroll
    for (int ii = 0; ii < 8; ii++) {
        float z = zacc[ii], s = sacc[ii];
#pragma unroll
        for (int m = 8; m; m >>= 1) {
            z += __shfl_xor_sync(0xffffffffu, z, m);
            s += __shfl_xor_sync(0xffffffffu, s, m);
        }
        if (tx == 0) {
            int gi = ibase + ty * 8 + ii;
            g_Zp[blockIdx.y * N2 + gi] = z;
            g_Sp[blockIdx.y * N2 + gi] = s;
        }
    }
}

// ---------------- kernel 4: deterministic final reduction ----------------
__global__ void finalize_kernel(float* __restrict__ out) {
    __shared__ float red[256];
    float local = 0.f;
    for (int i = threadIdx.x; i < N2; i += 256) {
        float Z = 0.f, S = 0.f;
#pragma unroll
        for (int p = 0; p < JSPLITS; p++) {
            Z += g_Zp[p * N2 + i];
            S += g_Sp[p * N2 + i];
        }
        local += S / g_cnt[i] - logf(Z);
    }
    red[threadIdx.x] = local;
    __syncthreads();
    for (int s = 128; s; s >>= 1) {
        if (threadIdx.x < s) red[threadIdx.x] += red[threadIdx.x + s];
        __syncthreads();
    }
    if (threadIdx.x == 0) out[0] = -red[0] / (float)N2;
}

// ---------------- launch ----------------
extern "C" void kernel_launch(void* const* d_in, const int* in_sizes, int n_in,
                              void* d_out, int out_size) {
    const float*     zi = (const float*)d_in[0];
    const float*     zj = (const float*)d_in[1];
    const long long* y  = (const long long*)d_in[2];
    float* out = (float*)d_out;

    // >48KB dynamic smem opt-in (immediate host call; not a graph node)
    cudaFuncSetAttribute(sim_kernel,
                         cudaFuncAttributeMaxDynamicSharedMemorySize,
                         (int)sizeof(MainSmem));

    normalize_kernel<<<N2 / 8, 256>>>(zi, zj, y);
    cnt_kernel<<<N2 / 256, 256>>>();
    sim_kernel<<<dim3(N2 / BI, JSPLITS), 256, sizeof(MainSmem)>>>();
    finalize_kernel<<<1, 256>>>(out);
}

// round 5
// speedup vs baseline: 4.9692x; 4.9692x over previous
#include <cuda_runtime.h>
#include <cuda_bf16.h>
#include <math.h>
#include <stdint.h>

#define N2 4096
#define NB 2048
#define DK 128
#define TAU_INV 10.0f
#define TM 128
#define TN 128
#define JSPLITS 32
#define LDA 136            // bf16 elements per smem row (128 + 8 pad)

// ---------------- device scratch ----------------
__device__ uint4 g_Q4[(N2 * DK) / 8];    // normalized rows, bf16, 16B-aligned
__device__ int   g_lbl[N2];
__device__ float g_cnt[N2];
__device__ float g_Zp[JSPLITS * N2];
__device__ float g_Sp[JSPLITS * N2];
__device__ float g_part[16];

// ---------------- kernel 1: normalize + bf16 convert (register-only pack) --
__global__ void normalize_kernel(const float* __restrict__ zi,
                                 const float* __restrict__ zj,
                                 const long long* __restrict__ y) {
    int row  = blockIdx.x * 8 + (threadIdx.x >> 5);
    int lane = threadIdx.x & 31;
    const float* src = (row < NB) ? (zi + (size_t)row * DK)
                                  : (zj + (size_t)(row - NB) * DK);
    float4 v = ((const float4*)src)[lane];
    float ss = v.x * v.x + v.y * v.y + v.z * v.z + v.w * v.w;
#pragma unroll
    for (int m = 16; m; m >>= 1) ss += __shfl_xor_sync(0xffffffffu, ss, m);
    float inv = rsqrtf(fmaxf(ss, 1e-30f));
    uint32_t p01, p23;
    // cvt d, a, b -> d.hi = a, d.lo = b  (lo must be the even element)
    asm("cvt.rn.bf16x2.f32 %0, %1, %2;" : "=r"(p01)
        : "f"(v.y * inv), "f"(v.x * inv));
    asm("cvt.rn.bf16x2.f32 %0, %1, %2;" : "=r"(p23)
        : "f"(v.w * inv), "f"(v.z * inv));
    uint32_t* q32 = (uint32_t*)g_Q4;
    q32[row * 64 + 2 * lane + 0] = p01;
    q32[row * 64 + 2 * lane + 1] = p23;
    if (lane == 0) g_lbl[row] = (int)y[row & (NB - 1)];
}

// ---------------- kernel 2: positive counts (index-guarded histogram) ------
__global__ void cnt_kernel() {
    __shared__ int hist[16];
    if (threadIdx.x < 16) hist[threadIdx.x] = 0;
    __syncthreads();
    for (int t = threadIdx.x; t < N2; t += 256)
        atomicAdd(&hist[g_lbl[t] & 15], 1);
    __syncthreads();
    for (int t = threadIdx.x; t < N2; t += 256)
        g_cnt[t] = (float)(hist[g_lbl[t] & 15] - 1);
}

// ---------------- kernel 3: bf16 HMMA sim + fused softmax stats ------------
#define SM_A   0
#define SM_B   (TM * LDA * 2)                 // 34816
#define SM_LI  (SM_B + TN * LDA * 2)          // 69632
#define SM_LJ  (SM_LI + 512)                  // 70144
#define SM_ZR  (SM_LJ + 512)                  // 70656  float[4][128]
#define SM_SR  (SM_ZR + 2048)                 // 72704  float[4][128]
#define SM_TOTAL (SM_SR + 2048)               // 74752

__global__ void __launch_bounds__(256) sim_kernel() {
    extern __shared__ char smem[];
    __nv_bfloat16* sA = (__nv_bfloat16*)(smem + SM_A);
    __nv_bfloat16* sB = (__nv_bfloat16*)(smem + SM_B);
    int*   li = (int*)(smem + SM_LI);
    int*   lj = (int*)(smem + SM_LJ);
    float* zr = (float*)(smem + SM_ZR);
    float* sr = (float*)(smem + SM_SR);

    const int tid  = threadIdx.x;
    const int wid  = tid >> 5, lane = tid & 31;
    const int ibase = blockIdx.x * TM, jbase = blockIdx.y * TN;

    // ---- load tiles (A row-major, B n-major; LDA-padded) ----
    {
        int r0 = tid >> 4, ch = tid & 15;   // 16 chunks of 16B per 128-elem row
#pragma unroll
        for (int it = 0; it < 8; it++) {
            int r = r0 + it * 16;
            uint4 va = g_Q4[(size_t)(ibase + r) * (DK / 8) + ch];
            *(uint4*)((char*)sA + r * (LDA * 2) + ch * 16) = va;
            uint4 vb = g_Q4[(size_t)(jbase + r) * (DK / 8) + ch];
            *(uint4*)((char*)sB + r * (LDA * 2) + ch * 16) = vb;
        }
    }
    if (tid < TM) li[tid] = g_lbl[ibase + tid];
    else if (tid < TM + TN) lj[tid - TM] = g_lbl[jbase + tid - TM];
    __syncthreads();

    // ---- warp tiling: 2 (m) x 4 (n) warps; warp tile 64x32 ----
    const int wy = wid >> 2, wx = wid & 3;
    const int m0w = wy * 64, n0w = wx * 32;
    const int g = lane >> 2, tq = lane & 3;

    float acc[4][4][4];
#pragma unroll
    for (int mt = 0; mt < 4; mt++)
#pragma unroll
        for (int nt = 0; nt < 4; nt++)
#pragma unroll
            for (int e = 0; e < 4; e++) acc[mt][nt][e] = 0.f;

#pragma unroll
    for (int ks = 0; ks < 8; ks++) {
        const int kk = ks * 16;
        // A fragments: a0={A[r][2t..]}, a1=+8rows, a2=+8k, a3=both (LDS.32 each)
        uint32_t Af[4][4];
#pragma unroll
        for (int mt = 0; mt < 4; mt++) {
            const __nv_bfloat16* base = &sA[(m0w + mt * 16 + g) * LDA + kk + 2 * tq];
            Af[mt][0] = *(const uint32_t*)(base);
            Af[mt][1] = *(const uint32_t*)(base + 8 * LDA);
            Af[mt][2] = *(const uint32_t*)(base + 8);
            Af[mt][3] = *(const uint32_t*)(base + 8 * LDA + 8);
        }
        // B fragments: b0={B[2t][n=g]} -> word at sB[n*LDA + k], b1=+8k
        uint32_t Bf[4][2];
#pragma unroll
        for (int nt = 0; nt < 4; nt++) {
            const __nv_bfloat16* base = &sB[(n0w + nt * 8 + g) * LDA + kk + 2 * tq];
            Bf[nt][0] = *(const uint32_t*)(base);
            Bf[nt][1] = *(const uint32_t*)(base + 8);
        }
#pragma unroll
        for (int mt = 0; mt < 4; mt++)
#pragma unroll
            for (int nt = 0; nt < 4; nt++) {
                asm volatile(
                    "mma.sync.aligned.m16n8k16.row.col.f32.bf16.bf16.f32 "
                    "{%0,%1,%2,%3}, {%4,%5,%6,%7}, {%8,%9}, {%0,%1,%2,%3};"
                    : "+f"(acc[mt][nt][0]), "+f"(acc[mt][nt][1]),
                      "+f"(acc[mt][nt][2]), "+f"(acc[mt][nt][3])
                    : "r"(Af[mt][0]), "r"(Af[mt][1]),
                      "r"(Af[mt][2]), "r"(Af[mt][3]),
                      "r"(Bf[nt][0]), "r"(Bf[nt][1]));
            }
    }

    // ---- fused epilogue: per-row Z (sum exp) and S (masked logit sum) ----
#pragma unroll
    for (int mt = 0; mt < 4; mt++) {
        int rl0 = m0w + mt * 16 + g;
        int rl1 = rl0 + 8;
        int gi0 = ibase + rl0, gi1 = ibase + rl1;
        int l0 = li[rl0], l1 = li[rl1];
        float z0 = 0.f, s0 = 0.f, z1 = 0.f, s1 = 0.f;
#pragma unroll
        for (int nt = 0; nt < 4; nt++) {
            int cb = n0w + nt * 8 + 2 * tq;
#pragma unroll
            for (int e = 0; e < 2; e++) {
                int col = cb + e, gj = jbase + col, ljv = lj[col];
                float lg0 = acc[mt][nt][e] * TAU_INV;
                if (gi0 != gj) {
                    z0 += __expf(lg0);
                    if (ljv == l0) s0 += lg0;
                }
                float lg1 = acc[mt][nt][2 + e] * TAU_INV;
                if (gi1 != gj) {
                    z1 += __expf(lg1);
                    if (ljv == l1) s1 += lg1;
                }
            }
        }
#pragma unroll
        for (int m = 1; m <= 2; m <<= 1) {
            z0 += __shfl_xor_sync(0xffffffffu, z0, m);
            s0 += __shfl_xor_sync(0xffffffffu, s0, m);
            z1 += __shfl_xor_sync(0xffffffffu, z1, m);
            s1 += __shfl_xor_sync(0xffffffffu, s1, m);
        }
        if (tq == 0) {
            zr[wx * 128 + rl0] = z0;  sr[wx * 128 + rl0] = s0;
            zr[wx * 128 + rl1] = z1;  sr[wx * 128 + rl1] = s1;
        }
    }
    __syncthreads();

    if (tid < TM) {
        float Z = 0.f, S = 0.f;
#pragma unroll
        for (int w = 0; w < 4; w++) {
            Z += zr[w * 128 + tid];
            S += sr[w * 128 + tid];
        }
        g_Zp[blockIdx.y * N2 + ibase + tid] = Z;
        g_Sp[blockIdx.y * N2 + ibase + tid] = S;
    }
}

// ---------------- kernels 4/5: parallel deterministic reduction ------------
__global__ void fin1_kernel() {
    __shared__ float red[256];
    int i = blockIdx.x * 256 + threadIdx.x;
    float Z = 0.f, S = 0.f;
#pragma unroll
    for (int p = 0; p < JSPLITS; p++) {
        Z += g_Zp[p * N2 + i];
        S += g_Sp[p * N2 + i];
    }
    red[threadIdx.x] = S / g_cnt[i] - logf(Z);
    __syncthreads();
    for (int s = 128; s; s >>= 1) {
        if (threadIdx.x < s) red[threadIdx.x] += red[threadIdx.x + s];
        __syncthreads();
    }
    if (threadIdx.x == 0) g_part[blockIdx.x] = red[0];
}

__global__ void fin2_kernel(float* __restrict__ out) {
    float v = (threadIdx.x < 16) ? g_part[threadIdx.x] : 0.f;
#pragma unroll
    for (int m = 16; m; m >>= 1) v += __shfl_xor_sync(0xffffffffu, v, m);
    if (threadIdx.x == 0) out[0] = -v / (float)N2;
}

// ---------------- launch ----------------
extern "C" void kernel_launch(void* const* d_in, const int* in_sizes, int n_in,
                              void* d_out, int out_size) {
    const float*     zi = (const float*)d_in[0];
    const float*     zj = (const float*)d_in[1];
    const long long* y  = (const long long*)d_in[2];
    float* out = (float*)d_out;

    cudaFuncSetAttribute(sim_kernel,
                         cudaFuncAttributeMaxDynamicSharedMemorySize, SM_TOTAL);

    normalize_kernel<<<N2 / 8, 256>>>(zi, zj, y);
    cnt_kernel<<<1, 256>>>();
    sim_kernel<<<dim3(N2 / TM, N2 / TN), 256, SM_TOTAL>>>();
    fin1_kernel<<<16, 256>>>();
    fin2_kernel<<<1, 32>>>(out);
}

// round 6
// speedup vs baseline: 6.3087x; 1.2696x over previous
#include <cuda_runtime.h>
#include <cuda_bf16.h>
#include <math.h>
#include <stdint.h>

#define N2 4096
#define NB 2048
#define DK 128
#define TAU_INV 10.0f
#define TM 128
#define TN 128
#define NT 32               // number of 128-row tiles
#define NPAIRS (NT * (NT + 1) / 2)   // 528
#define LDA 136             // bf16 elements per smem row (128 + 8 pad)

// ---------------- device scratch ----------------
__device__ uint4 g_Q4[(N2 * DK) / 8];    // normalized rows, bf16, 16B-aligned
__device__ int   g_lbl[N2];
__device__ float g_Zp[N2 * NT];          // [row][slot] contiguous per row
__device__ float g_Sp[N2 * NT];
__device__ float g_part[16];

// ---------------- kernel 1: normalize + bf16 convert -----------------------
__global__ void normalize_kernel(const float* __restrict__ zi,
                                 const float* __restrict__ zj,
                                 const long long* __restrict__ y) {
    int row  = blockIdx.x * 8 + (threadIdx.x >> 5);
    int lane = threadIdx.x & 31;
    const float* src = (row < NB) ? (zi + (size_t)row * DK)
                                  : (zj + (size_t)(row - NB) * DK);
    float4 v = ((const float4*)src)[lane];
    float ss = v.x * v.x + v.y * v.y + v.z * v.z + v.w * v.w;
#pragma unroll
    for (int m = 16; m; m >>= 1) ss += __shfl_xor_sync(0xffffffffu, ss, m);
    float inv = rsqrtf(fmaxf(ss, 1e-30f));
    uint32_t p01, p23;
    asm("cvt.rn.bf16x2.f32 %0, %1, %2;" : "=r"(p01)
        : "f"(v.y * inv), "f"(v.x * inv));
    asm("cvt.rn.bf16x2.f32 %0, %1, %2;" : "=r"(p23)
        : "f"(v.w * inv), "f"(v.z * inv));
    uint32_t* q32 = (uint32_t*)g_Q4;
    q32[row * 64 + 2 * lane + 0] = p01;
    q32[row * 64 + 2 * lane + 1] = p23;
    if (lane == 0) g_lbl[row] = (int)y[row & (NB - 1)];
}

// ---------------- kernel 2: symmetric bf16 HMMA sim + fused stats ----------
#define SM_A   0
#define SM_B   (TM * LDA * 2)                 // 34816
#define SM_LI  (SM_B + TN * LDA * 2)          // 69632
#define SM_LJ  (SM_LI + 512)                  // 70144
#define SM_ZR  (SM_LJ + 512)                  // 70656  float[4][128]
#define SM_SR  (SM_ZR + 2048)                 // 72704  float[4][128]
#define SM_CZ  (SM_SR + 2048)                 // 74752  float[2][128]
#define SM_CS  (SM_CZ + 1024)                 // 75776  float[2][128]
#define SM_TOTAL (SM_CS + 1024)               // 76800

__global__ void __launch_bounds__(256, 2) sim_kernel() {
    extern __shared__ char smem[];
    __nv_bfloat16* sA = (__nv_bfloat16*)(smem + SM_A);
    __nv_bfloat16* sB = (__nv_bfloat16*)(smem + SM_B);
    int*   li = (int*)(smem + SM_LI);
    int*   lj = (int*)(smem + SM_LJ);
    float* zr = (float*)(smem + SM_ZR);
    float* sr = (float*)(smem + SM_SR);
    float* cz = (float*)(smem + SM_CZ);
    float* cs = (float*)(smem + SM_CS);

    // triangular pair decode: t = J(J+1)/2 + I, 0 <= I <= J < 32
    int t = blockIdx.x;
    int J = (int)((sqrtf(8.0f * t + 1.0f) - 1.0f) * 0.5f);
    while ((J + 1) * (J + 2) / 2 <= t) ++J;
    while (J * (J + 1) / 2 > t) --J;
    int I = t - J * (J + 1) / 2;
    const bool offdiag = (I != J);

    const int tid  = threadIdx.x;
    const int wid  = tid >> 5, lane = tid & 31;
    const int ibase = I * TM, jbase = J * TN;

    // ---- load tiles ----
    {
        int r0 = tid >> 4, ch = tid & 15;
#pragma unroll
        for (int it = 0; it < 8; it++) {
            int r = r0 + it * 16;
            uint4 va = g_Q4[(size_t)(ibase + r) * (DK / 8) + ch];
            *(uint4*)((char*)sA + r * (LDA * 2) + ch * 16) = va;
            uint4 vb = g_Q4[(size_t)(jbase + r) * (DK / 8) + ch];
            *(uint4*)((char*)sB + r * (LDA * 2) + ch * 16) = vb;
        }
    }
    if (tid < TM) li[tid] = g_lbl[ibase + tid];
    else if (tid < TM + TN) lj[tid - TM] = g_lbl[jbase + tid - TM];
    __syncthreads();

    // ---- warp tiling: 2 (m) x 4 (n); warp tile 64x32 ----
    const int wy = wid >> 2, wx = wid & 3;
    const int m0w = wy * 64, n0w = wx * 32;
    const int g = lane >> 2, tq = lane & 3;

    float acc[4][4][4];
#pragma unroll
    for (int mt = 0; mt < 4; mt++)
#pragma unroll
        for (int nt = 0; nt < 4; nt++)
#pragma unroll
            for (int e = 0; e < 4; e++) acc[mt][nt][e] = 0.f;

#pragma unroll
    for (int ks = 0; ks < 8; ks++) {
        const int kk = ks * 16;
        uint32_t Af[4][4];
#pragma unroll
        for (int mt = 0; mt < 4; mt++) {
            const __nv_bfloat16* base = &sA[(m0w + mt * 16 + g) * LDA + kk + 2 * tq];
            Af[mt][0] = *(const uint32_t*)(base);
            Af[mt][1] = *(const uint32_t*)(base + 8 * LDA);
            Af[mt][2] = *(const uint32_t*)(base + 8);
            Af[mt][3] = *(const uint32_t*)(base + 8 * LDA + 8);
        }
        uint32_t Bf[4][2];
#pragma unroll
        for (int nt = 0; nt < 4; nt++) {
            const __nv_bfloat16* base = &sB[(n0w + nt * 8 + g) * LDA + kk + 2 * tq];
            Bf[nt][0] = *(const uint32_t*)(base);
            Bf[nt][1] = *(const uint32_t*)(base + 8);
        }
#pragma unroll
        for (int mt = 0; mt < 4; mt++)
#pragma unroll
            for (int nt = 0; nt < 4; nt++) {
                asm volatile(
                    "mma.sync.aligned.m16n8k16.row.col.f32.bf16.bf16.f32 "
                    "{%0,%1,%2,%3}, {%4,%5,%6,%7}, {%8,%9}, {%0,%1,%2,%3};"
                    : "+f"(acc[mt][nt][0]), "+f"(acc[mt][nt][1]),
                      "+f"(acc[mt][nt][2]), "+f"(acc[mt][nt][3])
                    : "r"(Af[mt][0]), "r"(Af[mt][1]),
                      "r"(Af[mt][2]), "r"(Af[mt][3]),
                      "r"(Bf[nt][0]), "r"(Bf[nt][1]));
            }
    }

    // ---- fused epilogue: i-row stats + (offdiag) j-col stats ----
    float zc[8], sc[8];
#pragma unroll
    for (int q = 0; q < 8; q++) { zc[q] = 0.f; sc[q] = 0.f; }

#pragma unroll
    for (int mt = 0; mt < 4; mt++) {
        int rl0 = m0w + mt * 16 + g;
        int rl1 = rl0 + 8;
        int gi0 = ibase + rl0, gi1 = ibase + rl1;
        int l0 = li[rl0], l1 = li[rl1];
        float z0 = 0.f, s0 = 0.f, z1 = 0.f, s1 = 0.f;
#pragma unroll
        for (int nt = 0; nt < 4; nt++) {
            int cb = n0w + nt * 8 + 2 * tq;
#pragma unroll
            for (int e = 0; e < 2; e++) {
                int col = cb + e, gj = jbase + col, ljv = lj[col];
                float lg0 = acc[mt][nt][e] * TAU_INV;
                float lg1 = acc[mt][nt][2 + e] * TAU_INV;
                float e0 = 0.f, e1 = 0.f, m0 = 0.f, m1 = 0.f;
                if (gi0 != gj) {
                    e0 = __expf(lg0);
                    if (ljv == l0) m0 = lg0;
                }
                if (gi1 != gj) {
                    e1 = __expf(lg1);
                    if (ljv == l1) m1 = lg1;
                }
                z0 += e0; s0 += m0;
                z1 += e1; s1 += m1;
                if (offdiag) {
                    zc[nt * 2 + e] += e0 + e1;
                    sc[nt * 2 + e] += m0 + m1;
                }
            }
        }
#pragma unroll
        for (int m = 1; m <= 2; m <<= 1) {
            z0 += __shfl_xor_sync(0xffffffffu, z0, m);
            s0 += __shfl_xor_sync(0xffffffffu, s0, m);
            z1 += __shfl_xor_sync(0xffffffffu, z1, m);
            s1 += __shfl_xor_sync(0xffffffffu, s1, m);
        }
        if (tq == 0) {
            zr[wx * 128 + rl0] = z0;  sr[wx * 128 + rl0] = s0;
            zr[wx * 128 + rl1] = z1;  sr[wx * 128 + rl1] = s1;
        }
    }

    if (offdiag) {
        // reduce col partials over the 8 g-lanes (same tq share columns)
#pragma unroll
        for (int m = 4; m <= 16; m <<= 1)
#pragma unroll
            for (int q = 0; q < 8; q++) {
                zc[q] += __shfl_xor_sync(0xffffffffu, zc[q], m);
                sc[q] += __shfl_xor_sync(0xffffffffu, sc[q], m);
            }
        if (g == 0) {
#pragma unroll
            for (int nt = 0; nt < 4; nt++)
#pragma unroll
                for (int e = 0; e < 2; e++) {
                    int col = n0w + nt * 8 + 2 * tq + e;
                    cz[wy * 128 + col] = zc[nt * 2 + e];
                    cs[wy * 128 + col] = sc[nt * 2 + e];
                }
        }
    }
    __syncthreads();

    if (tid < TM) {
        float Z = 0.f, S = 0.f;
#pragma unroll
        for (int w = 0; w < 4; w++) {
            Z += zr[w * 128 + tid];
            S += sr[w * 128 + tid];
        }
        g_Zp[(ibase + tid) * NT + J] = Z;
        g_Sp[(ibase + tid) * NT + J] = S;
        if (offdiag) {
            float Zc = cz[tid] + cz[128 + tid];
            float Sc = cs[tid] + cs[128 + tid];
            g_Zp[(jbase + tid) * NT + I] = Zc;
            g_Sp[(jbase + tid) * NT + I] = Sc;
        }
    }
}

// ---------------- kernel 3: reduction + per-row finalize (hist fused) ------
__global__ void fin1_kernel() {
    __shared__ float red[256];
    __shared__ int hist[16];
    if (threadIdx.x < 16) hist[threadIdx.x] = 0;
    __syncthreads();
    for (int q = threadIdx.x; q < N2; q += 256)
        atomicAdd(&hist[g_lbl[q] & 15], 1);
    __syncthreads();

    int i = blockIdx.x * 256 + threadIdx.x;
    const float4* zp4 = (const float4*)&g_Zp[i * NT];
    const float4* sp4 = (const float4*)&g_Sp[i * NT];
    float Z = 0.f, S = 0.f;
#pragma unroll
    for (int q = 0; q < 8; q++) {
        float4 a = zp4[q], b = sp4[q];
        Z += a.x + a.y + a.z + a.w;
        S += b.x + b.y + b.z + b.w;
    }
    float cnt = (float)(hist[g_lbl[i] & 15] - 1);
    red[threadIdx.x] = S / cnt - logf(Z);
    __syncthreads();
    for (int s = 128; s; s >>= 1) {
        if (threadIdx.x < s) red[threadIdx.x] += red[threadIdx.x + s];
        __syncthreads();
    }
    if (threadIdx.x == 0) g_part[blockIdx.x] = red[0];
}

__global__ void fin2_kernel(float* __restrict__ out) {
    float v = (threadIdx.x < 16) ? g_part[threadIdx.x] : 0.f;
#pragma unroll
    for (int m = 16; m; m >>= 1) v += __shfl_xor_sync(0xffffffffu, v, m);
    if (threadIdx.x == 0) out[0] = -v / (float)N2;
}

// ---------------- launch ----------------
extern "C" void kernel_launch(void* const* d_in, const int* in_sizes, int n_in,
                              void* d_out, int out_size) {
    const float*     zi = (const float*)d_in[0];
    const float*     zj = (const float*)d_in[1];
    const long long* y  = (const long long*)d_in[2];
    float* out = (float*)d_out;

    cudaFuncSetAttribute(sim_kernel,
                         cudaFuncAttributeMaxDynamicSharedMemorySize, SM_TOTAL);

    normalize_kernel<<<N2 / 8, 256>>>(zi, zj, y);
    sim_kernel<<<NPAIRS, 256, SM_TOTAL>>>();
    fin1_kernel<<<16, 256>>>();
    fin2_kernel<<<1, 32>>>(out);
}

// round 7
// speedup vs baseline: 6.3640x; 1.0088x over previous
#include <cuda_runtime.h>
#include <cuda_bf16.h>
#include <math.h>
#include <stdint.h>

#define N2 4096
#define NB 2048
#define DK 128
#define TAU_INV 10.0f
#define TM 128
#define TN 128
#define NT 32               // number of 128-row tiles
#define NPAIRS (NT * (NT + 1) / 2)   // 528
#define LDA 136             // bf16 elements per smem row (128 + 8 pad)

// ---------------- device scratch ----------------
__device__ uint4 g_Q4[(N2 * DK) / 8];    // normalized rows, bf16, 16B-aligned
__device__ int   g_lbl[N2];
__device__ float g_Zp[N2 * NT];          // [row][slot] contiguous per row
__device__ float g_Sp[N2 * NT];
__device__ float g_part[16];
__device__ int   g_ctr;

// ---------------- kernel 1: normalize + bf16 convert -----------------------
__global__ void normalize_kernel(const float* __restrict__ zi,
                                 const float* __restrict__ zj,
                                 const long long* __restrict__ y) {
    if (blockIdx.x == 0 && threadIdx.x == 0) g_ctr = 0;   // replay-safe reset
    int row  = blockIdx.x * 8 + (threadIdx.x >> 5);
    int lane = threadIdx.x & 31;
    const float* src = (row < NB) ? (zi + (size_t)row * DK)
                                  : (zj + (size_t)(row - NB) * DK);
    float4 v = ((const float4*)src)[lane];
    float ss = v.x * v.x + v.y * v.y + v.z * v.z + v.w * v.w;
#pragma unroll
    for (int m = 16; m; m >>= 1) ss += __shfl_xor_sync(0xffffffffu, ss, m);
    float inv = rsqrtf(fmaxf(ss, 1e-30f));
    uint32_t p01, p23;
    asm("cvt.rn.bf16x2.f32 %0, %1, %2;" : "=r"(p01)
        : "f"(v.y * inv), "f"(v.x * inv));
    asm("cvt.rn.bf16x2.f32 %0, %1, %2;" : "=r"(p23)
        : "f"(v.w * inv), "f"(v.z * inv));
    uint32_t* q32 = (uint32_t*)g_Q4;
    q32[row * 64 + 2 * lane + 0] = p01;
    q32[row * 64 + 2 * lane + 1] = p23;
    if (lane == 0) g_lbl[row] = (int)y[row & (NB - 1)];
}

// ---------------- kernel 2: symmetric bf16 HMMA sim + fused stats ----------
#define SM_A   0
#define SM_B   (TM * LDA * 2)                 // 34816
#define SM_LI  (SM_B + TN * LDA * 2)          // 69632
#define SM_LJ  (SM_LI + 512)                  // 70144
#define SM_ZR  (SM_LJ + 512)                  // 70656  float[4][128]
#define SM_SR  (SM_ZR + 2048)                 // 72704  float[4][128]
#define SM_CZ  (SM_SR + 2048)                 // 74752  float[2][128]
#define SM_CS  (SM_CZ + 1024)                 // 75776  float[2][128]
#define SM_TOTAL (SM_CS + 1024)               // 76800

__global__ void __launch_bounds__(256, 2) sim_kernel() {
    extern __shared__ char smem[];
    __nv_bfloat16* sA = (__nv_bfloat16*)(smem + SM_A);
    __nv_bfloat16* sB = (__nv_bfloat16*)(smem + SM_B);
    int*   li = (int*)(smem + SM_LI);
    int*   lj = (int*)(smem + SM_LJ);
    float* zr = (float*)(smem + SM_ZR);
    float* sr = (float*)(smem + SM_SR);
    float* cz = (float*)(smem + SM_CZ);
    float* cs = (float*)(smem + SM_CS);

    // triangular pair decode: t = J(J+1)/2 + I, 0 <= I <= J < 32
    int t = blockIdx.x;
    int J = (int)((sqrtf(8.0f * t + 1.0f) - 1.0f) * 0.5f);
    while ((J + 1) * (J + 2) / 2 <= t) ++J;
    while (J * (J + 1) / 2 > t) --J;
    int I = t - J * (J + 1) / 2;
    const bool offdiag = (I != J);

    const int tid  = threadIdx.x;
    const int wid  = tid >> 5, lane = tid & 31;
    const int ibase = I * TM, jbase = J * TN;

    // ---- load tiles ----
    {
        int r0 = tid >> 4, ch = tid & 15;
#pragma unroll
        for (int it = 0; it < 8; it++) {
            int r = r0 + it * 16;
            uint4 va = g_Q4[(size_t)(ibase + r) * (DK / 8) + ch];
            *(uint4*)((char*)sA + r * (LDA * 2) + ch * 16) = va;
            uint4 vb = g_Q4[(size_t)(jbase + r) * (DK / 8) + ch];
            *(uint4*)((char*)sB + r * (LDA * 2) + ch * 16) = vb;
        }
    }
    if (tid < TM) li[tid] = g_lbl[ibase + tid];
    else if (tid < TM + TN) lj[tid - TM] = g_lbl[jbase + tid - TM];
    __syncthreads();

    // ---- warp tiling: 2 (m) x 4 (n); warp tile 64x32 ----
    const int wy = wid >> 2, wx = wid & 3;
    const int m0w = wy * 64, n0w = wx * 32;
    const int g = lane >> 2, tq = lane & 3;

    float acc[4][4][4];
#pragma unroll
    for (int mt = 0; mt < 4; mt++)
#pragma unroll
        for (int nt = 0; nt < 4; nt++)
#pragma unroll
            for (int e = 0; e < 4; e++) acc[mt][nt][e] = 0.f;

#pragma unroll
    for (int ks = 0; ks < 8; ks++) {
        const int kk = ks * 16;
        uint32_t Af[4][4];
#pragma unroll
        for (int mt = 0; mt < 4; mt++) {
            const __nv_bfloat16* base = &sA[(m0w + mt * 16 + g) * LDA + kk + 2 * tq];
            Af[mt][0] = *(const uint32_t*)(base);
            Af[mt][1] = *(const uint32_t*)(base + 8 * LDA);
            Af[mt][2] = *(const uint32_t*)(base + 8);
            Af[mt][3] = *(const uint32_t*)(base + 8 * LDA + 8);
        }
        uint32_t Bf[4][2];
#pragma unroll
        for (int nt = 0; nt < 4; nt++) {
            const __nv_bfloat16* base = &sB[(n0w + nt * 8 + g) * LDA + kk + 2 * tq];
            Bf[nt][0] = *(const uint32_t*)(base);
            Bf[nt][1] = *(const uint32_t*)(base + 8);
        }
#pragma unroll
        for (int mt = 0; mt < 4; mt++)
#pragma unroll
            for (int nt = 0; nt < 4; nt++) {
                asm volatile(
                    "mma.sync.aligned.m16n8k16.row.col.f32.bf16.bf16.f32 "
                    "{%0,%1,%2,%3}, {%4,%5,%6,%7}, {%8,%9}, {%0,%1,%2,%3};"
                    : "+f"(acc[mt][nt][0]), "+f"(acc[mt][nt][1]),
                      "+f"(acc[mt][nt][2]), "+f"(acc[mt][nt][3])
                    : "r"(Af[mt][0]), "r"(Af[mt][1]),
                      "r"(Af[mt][2]), "r"(Af[mt][3]),
                      "r"(Bf[nt][0]), "r"(Bf[nt][1]));
            }
    }

    // ---- fused epilogue: i-row stats + (offdiag) j-col stats ----
    float zc[8], sc[8];
#pragma unroll
    for (int q = 0; q < 8; q++) { zc[q] = 0.f; sc[q] = 0.f; }

#pragma unroll
    for (int mt = 0; mt < 4; mt++) {
        int rl0 = m0w + mt * 16 + g;
        int rl1 = rl0 + 8;
        int gi0 = ibase + rl0, gi1 = ibase + rl1;
        int l0 = li[rl0], l1 = li[rl1];
        float z0 = 0.f, s0 = 0.f, z1 = 0.f, s1 = 0.f;
#pragma unroll
        for (int nt = 0; nt < 4; nt++) {
            int cb = n0w + nt * 8 + 2 * tq;
#pragma unroll
            for (int e = 0; e < 2; e++) {
                int col = cb + e, gj = jbase + col, ljv = lj[col];
                float lg0 = acc[mt][nt][e] * TAU_INV;
                float lg1 = acc[mt][nt][2 + e] * TAU_INV;
                float e0 = 0.f, e1 = 0.f, m0 = 0.f, m1 = 0.f;
                if (gi0 != gj) {
                    e0 = __expf(lg0);
                    if (ljv == l0) m0 = lg0;
                }
                if (gi1 != gj) {
                    e1 = __expf(lg1);
                    if (ljv == l1) m1 = lg1;
                }
                z0 += e0; s0 += m0;
                z1 += e1; s1 += m1;
                if (offdiag) {
                    zc[nt * 2 + e] += e0 + e1;
                    sc[nt * 2 + e] += m0 + m1;
                }
            }
        }
#pragma unroll
        for (int m = 1; m <= 2; m <<= 1) {
            z0 += __shfl_xor_sync(0xffffffffu, z0, m);
            s0 += __shfl_xor_sync(0xffffffffu, s0, m);
            z1 += __shfl_xor_sync(0xffffffffu, z1, m);
            s1 += __shfl_xor_sync(0xffffffffu, s1, m);
        }
        if (tq == 0) {
            zr[wx * 128 + rl0] = z0;  sr[wx * 128 + rl0] = s0;
            zr[wx * 128 + rl1] = z1;  sr[wx * 128 + rl1] = s1;
        }
    }

    if (offdiag) {
#pragma unroll
        for (int m = 4; m <= 16; m <<= 1)
#pragma unroll
            for (int q = 0; q < 8; q++) {
                zc[q] += __shfl_xor_sync(0xffffffffu, zc[q], m);
                sc[q] += __shfl_xor_sync(0xffffffffu, sc[q], m);
            }
        if (g == 0) {
#pragma unroll
            for (int nt = 0; nt < 4; nt++)
#pragma unroll
                for (int e = 0; e < 2; e++) {
                    int col = n0w + nt * 8 + 2 * tq + e;
                    cz[wy * 128 + col] = zc[nt * 2 + e];
                    cs[wy * 128 + col] = sc[nt * 2 + e];
                }
        }
    }
    __syncthreads();

    if (tid < TM) {
        float Z = 0.f, S = 0.f;
#pragma unroll
        for (int w = 0; w < 4; w++) {
            Z += zr[w * 128 + tid];
            S += sr[w * 128 + tid];
        }
        g_Zp[(ibase + tid) * NT + J] = Z;
        g_Sp[(ibase + tid) * NT + J] = S;
        if (offdiag) {
            float Zc = cz[tid] + cz[128 + tid];
            float Sc = cs[tid] + cs[128 + tid];
            g_Zp[(jbase + tid) * NT + I] = Zc;
            g_Sp[(jbase + tid) * NT + I] = Sc;
        }
    }
}

// ---------------- kernel 3: reduction + finalize (single kernel) -----------
__global__ void fin_kernel(float* __restrict__ out) {
    __shared__ float red[256];
    __shared__ int hist[16];
    __shared__ int amLast;
    if (threadIdx.x < 16) hist[threadIdx.x] = 0;
    __syncthreads();
    for (int q = threadIdx.x; q < N2; q += 256)
        atomicAdd(&hist[g_lbl[q] & 15], 1);
    __syncthreads();

    int i = blockIdx.x * 256 + threadIdx.x;
    const float4* zp4 = (const float4*)&g_Zp[i * NT];
    const float4* sp4 = (const float4*)&g_Sp[i * NT];
    float Z = 0.f, S = 0.f;
#pragma unroll
    for (int q = 0; q < 8; q++) {
        float4 a = zp4[q], b = sp4[q];
        Z += a.x + a.y + a.z + a.w;
        S += b.x + b.y + b.z + b.w;
    }
    float cnt = (float)(hist[g_lbl[i] & 15] - 1);
    red[threadIdx.x] = S / cnt - logf(Z);
    __syncthreads();
    for (int s = 128; s; s >>= 1) {
        if (threadIdx.x < s) red[threadIdx.x] += red[threadIdx.x + s];
        __syncthreads();
    }
    if (threadIdx.x == 0) {
        g_part[blockIdx.x] = red[0];
        __threadfence();
        amLast = (atomicAdd(&g_ctr, 1) == 15);
    }
    __syncthreads();
    if (amLast && threadIdx.x < 32) {
        float v = (threadIdx.x < 16) ? g_part[threadIdx.x] : 0.f;
#pragma unroll
        for (int m = 16; m; m >>= 1) v += __shfl_xor_sync(0xffffffffu, v, m);
        if (threadIdx.x == 0) out[0] = -v / (float)N2;
    }
}

// ---------------- launch ----------------
extern "C" void kernel_launch(void* const* d_in, const int* in_sizes, int n_in,
                              void* d_out, int out_size) {
    const float*     zi = (const float*)d_in[0];
    const float*     zj = (const float*)d_in[1];
    const long long* y  = (const long long*)d_in[2];
    float* out = (float*)d_out;

    cudaFuncSetAttribute(sim_kernel,
                         cudaFuncAttributeMaxDynamicSharedMemorySize, SM_TOTAL);

    normalize_kernel<<<N2 / 8, 256>>>(zi, zj, y);
    sim_kernel<<<NPAIRS, 256, SM_TOTAL>>>();
    fin_kernel<<<16, 256>>>(out);
}